// round 4
// baseline (speedup 1.0000x reference)
#include <cuda_runtime.h>
#include <math.h>

#define B_ 2
#define T_ 2048
#define E_ 2048
#define G_ 4
#define QPG_ 4
#define D_ 128
#define H_ (G_*QPG_)    // 16
#define NQ_ (H_*D_)     // 2048
#define NKV_ (2*G_*D_)  // 1024
#define M_ (B_*T_)      // 4096

typedef unsigned long long ull_t;

// ---- packed f32x2 helpers (Blackwell FFMA2) --------------------------------
__device__ __forceinline__ ull_t pack2(float lo, float hi) {
    ull_t r; asm("mov.b64 %0, {%1,%2};" : "=l"(r) : "f"(lo), "f"(hi)); return r;
}
__device__ __forceinline__ void unpack2(ull_t v, float& lo, float& hi) {
    asm("mov.b64 {%0,%1}, %2;" : "=f"(lo), "=f"(hi) : "l"(v));
}
__device__ __forceinline__ ull_t fma2(ull_t a, ull_t b, ull_t c) {
    ull_t d; asm("fma.rn.f32x2 %0, %1, %2, %3;" : "=l"(d) : "l"(a), "l"(b), "l"(c)); return d;
}
__device__ __forceinline__ ull_t mul2(ull_t a, ull_t b) {
    ull_t d; asm("mul.rn.f32x2 %0, %1, %2;" : "=l"(d) : "l"(a), "l"(b)); return d;
}

// Scratch (no cudaMalloc allowed): q, kv, attn_out
__device__ float g_q[(size_t)M_ * NQ_];     // 33.5 MB
__device__ float g_kv[(size_t)M_ * NKV_];   // 16.8 MB
__device__ float g_att[(size_t)M_ * NQ_];   // 33.5 MB

// ---------------------------------------------------------------------------
// FFMA2 fp32 GEMM: C[M,N] = A[M,K] @ W[K,N] (+ bias). Tiles 128x128x16,
// 256 threads, 8x8 microtile. A is stored DUPLICATED in smem ({a,a} pairs)
// so dup pairs come straight from ld.shared.v4; B pairs are natural
// consecutive floats. Inner loop: 6 LDS.128 + 32 FFMA2 per k, no MOV packs.
// ---------------------------------------------------------------------------
#define ASD 260   // floats per k-row of duplicated A (256 used + 4 pad)
#define WSD 132   // floats per k-row of W tile (128 used + 4 pad)

__global__ __launch_bounds__(256) void gemm_ffma2_kernel(
    const float* __restrict__ A, const float* __restrict__ W,
    const float* __restrict__ bias, float* __restrict__ C,
    int Nsz, int Ksz)
{
    constexpr int BK = 16;
    __shared__ __align__(16) float Asd[BK * ASD];  // 16.6 KB, dup A [k][2*m]
    __shared__ __align__(16) float Wst[BK * WSD];  // 8.4 KB,  [k][n]

    const int tid = threadIdx.x;
    const int tx = tid & 15, ty = tid >> 4;
    const int m0 = blockIdx.y * 128, n0 = blockIdx.x * 128;

    // load maps
    const int arow = tid >> 1;           // 0..127
    const int ak8  = (tid & 1) * 8;      // 0 or 8
    const int wk   = tid >> 4;           // 0..15
    const int wn   = (tid & 15) * 8;     // 0..120

    ull_t acc[8][4];
    #pragma unroll
    for (int i = 0; i < 8; i++)
        #pragma unroll
        for (int j = 0; j < 4; j++) acc[i][j] = 0ull;

    for (int k0 = 0; k0 < Ksz; k0 += BK) {
        // A tile: 2 float4 per thread, stored duplicated
        {
            const float* ar = &A[(size_t)(m0 + arow) * Ksz + k0 + ak8];
            float4 v0 = *(const float4*)(ar);
            float4 v1 = *(const float4*)(ar + 4);
            float2* d0 = (float2*)&Asd[(ak8 + 0) * ASD + 2 * arow];
            *(float2*)&Asd[(ak8 + 0) * ASD + 2 * arow] = make_float2(v0.x, v0.x);
            *(float2*)&Asd[(ak8 + 1) * ASD + 2 * arow] = make_float2(v0.y, v0.y);
            *(float2*)&Asd[(ak8 + 2) * ASD + 2 * arow] = make_float2(v0.z, v0.z);
            *(float2*)&Asd[(ak8 + 3) * ASD + 2 * arow] = make_float2(v0.w, v0.w);
            *(float2*)&Asd[(ak8 + 4) * ASD + 2 * arow] = make_float2(v1.x, v1.x);
            *(float2*)&Asd[(ak8 + 5) * ASD + 2 * arow] = make_float2(v1.y, v1.y);
            *(float2*)&Asd[(ak8 + 6) * ASD + 2 * arow] = make_float2(v1.z, v1.z);
            *(float2*)&Asd[(ak8 + 7) * ASD + 2 * arow] = make_float2(v1.w, v1.w);
            (void)d0;
        }
        // W tile: 2 float4 per thread
        {
            const float* wr = &W[(size_t)(k0 + wk) * Nsz + n0 + wn];
            *(float4*)&Wst[wk * WSD + wn]     = *(const float4*)(wr);
            *(float4*)&Wst[wk * WSD + wn + 4] = *(const float4*)(wr + 4);
        }
        __syncthreads();

        #pragma unroll
        for (int kk = 0; kk < BK; kk++) {
            const ulonglong2* ap = (const ulonglong2*)&Asd[kk * ASD + ty * 16];
            ulonglong2 a01 = ap[0], a23 = ap[1], a45 = ap[2], a67 = ap[3];
            const ulonglong2* bp = (const ulonglong2*)&Wst[kk * WSD + tx * 8];
            ulonglong2 b01 = bp[0], b23 = bp[1];
            ull_t ad[8] = {a01.x, a01.y, a23.x, a23.y, a45.x, a45.y, a67.x, a67.y};
            ull_t bd[4] = {b01.x, b01.y, b23.x, b23.y};
            #pragma unroll
            for (int i = 0; i < 8; i++)
                #pragma unroll
                for (int j = 0; j < 4; j++)
                    acc[i][j] = fma2(ad[i], bd[j], acc[i][j]);
        }
        __syncthreads();
    }

    // Epilogue
    #pragma unroll
    for (int i = 0; i < 8; i++) {
        int row = m0 + ty * 8 + i;
        int col = n0 + tx * 8;
        float o[8];
        #pragma unroll
        for (int j = 0; j < 4; j++) unpack2(acc[i][j], o[2 * j], o[2 * j + 1]);
        if (bias) {
            #pragma unroll
            for (int j = 0; j < 8; j++) o[j] += bias[col + j];
        }
        float* dst = &C[(size_t)row * Nsz + col];
        *(float4*)(dst)     = make_float4(o[0], o[1], o[2], o[3]);
        *(float4*)(dst + 4) = make_float4(o[4], o[5], o[6], o[7]);
    }
}

// ---------------------------------------------------------------------------
// Add sinusoidal PE into q (all 16 heads) and the K half of kv (4 groups).
// ---------------------------------------------------------------------------
__global__ __launch_bounds__(128) void add_pe_kernel(
    float* __restrict__ q, float* __restrict__ kv)
{
    int bt = blockIdx.x;
    int d  = threadIdx.x;
    int t  = bt % T_;
    int i2 = d & ~1;
    float inv = expf(-logf(10000.0f) * (float)i2 / (float)D_);
    float ang = (float)t * inv;
    float pe  = (d & 1) ? cosf(ang) : sinf(ang);

    float* qrow = q + (size_t)bt * NQ_;
    #pragma unroll
    for (int h = 0; h < H_; h++) qrow[h * D_ + d] += pe;

    float* kvrow = kv + (size_t)bt * NKV_;
    #pragma unroll
    for (int g = 0; g < G_; g++) kvrow[g * 2 * D_ + d] += pe;
}

// ---------------------------------------------------------------------------
// Flash attention, fp32 with FFMA2 PV. Block = (q-tile 64 rows, (b,head)).
// Smem: Qst[128][68] (d-major), Kst[128][68] (d-major; ALIASED by the
// DUPLICATED P tile Ss[64][130] during the PV phase), Vs[64][132].
// S-gemm 4x4 scalar microtile; PV 4x(4 pair) FFMA2 microtile.
// ---------------------------------------------------------------------------
#define SSD 130   // dup P row stride (2*64 used + 2 pad)

__global__ __launch_bounds__(256) void attn_kernel(
    const float* __restrict__ q, const float* __restrict__ kv,
    float* __restrict__ out)
{
    __shared__ __align__(16) float Qst[128 * 68];
    __shared__ __align__(16) float Kst[128 * 68];   // holds dup Ss[64][130] in PV phase
    __shared__ __align__(16) float Vs [64 * 132];
    float* Ss = Kst;

    const int qt = blockIdx.x;
    const int bh = blockIdx.y;
    const int b = bh / H_, h = bh % H_, g = h / QPG_;
    const int q0 = qt * 64;

    const int tid = threadIdx.x;
    const int tx = tid & 15, ty = tid >> 4;
    const float scale = 0.088388347648318447f;   // 1/sqrt(128)

    // Load Q tile transposed (d-major)
    for (int it = tid; it < 64 * 32; it += 256) {
        int row = it >> 5;
        int dg  = (it & 31) * 4;
        float4 v = *(const float4*)&q[(size_t)(b * T_ + q0 + row) * NQ_ + h * D_ + dg];
        Qst[(dg + 0) * 68 + row] = v.x;
        Qst[(dg + 1) * 68 + row] = v.y;
        Qst[(dg + 2) * 68 + row] = v.z;
        Qst[(dg + 3) * 68 + row] = v.w;
    }

    ull_t acc2[4][4];
    #pragma unroll
    for (int i = 0; i < 4; i++)
        #pragma unroll
        for (int j = 0; j < 4; j++) acc2[i][j] = 0ull;
    float mrun[4], lrun[4];
    #pragma unroll
    for (int i = 0; i < 4; i++) { mrun[i] = -INFINITY; lrun[i] = 0.0f; }

    for (int kt = 0; kt <= qt; kt++) {
        const int k0 = kt * 64;
        __syncthreads();   // previous PV done (and Q load on first iter)

        // Load K transposed + V row-major
        for (int it = tid; it < 64 * 32; it += 256) {
            int row = it >> 5;
            int dg  = (it & 31) * 4;
            const float* base = &kv[(size_t)(b * T_ + k0 + row) * NKV_ + g * 2 * D_];
            float4 kvv = *(const float4*)(base + dg);
            Kst[(dg + 0) * 68 + row] = kvv.x;
            Kst[(dg + 1) * 68 + row] = kvv.y;
            Kst[(dg + 2) * 68 + row] = kvv.z;
            Kst[(dg + 3) * 68 + row] = kvv.w;
            *(float4*)&Vs[row * 132 + dg] = *(const float4*)(base + D_ + dg);
        }
        __syncthreads();

        // S = Q @ K^T (4x4 per thread, scalar FFMA)
        float s[4][4] = {};
        #pragma unroll 4
        for (int d = 0; d < 128; d++) {
            float4 a  = *(const float4*)&Qst[d * 68 + ty * 4];
            float4 bv = *(const float4*)&Kst[d * 68 + tx * 4];
            float ar[4] = {a.x, a.y, a.z, a.w};
            float br[4] = {bv.x, bv.y, bv.z, bv.w};
            #pragma unroll
            for (int i = 0; i < 4; i++)
                #pragma unroll
                for (int j = 0; j < 4; j++)
                    s[i][j] = fmaf(ar[i], br[j], s[i][j]);
        }

        const bool diag = (kt == qt);
        #pragma unroll
        for (int i = 0; i < 4; i++)
            #pragma unroll
            for (int j = 0; j < 4; j++) {
                s[i][j] *= scale;
                if (diag && (tx * 4 + j) > (ty * 4 + i)) s[i][j] = -INFINITY;
            }

        // Online softmax update (stats replicated across the 16 lanes of ty)
        float cfix[4], nm[4];
        #pragma unroll
        for (int i = 0; i < 4; i++) {
            float lm = fmaxf(fmaxf(s[i][0], s[i][1]), fmaxf(s[i][2], s[i][3]));
            #pragma unroll
            for (int m = 8; m >= 1; m >>= 1)
                lm = fmaxf(lm, __shfl_xor_sync(0xffffffffu, lm, m));
            float newm = fmaxf(mrun[i], lm);
            cfix[i] = __expf(mrun[i] - newm);
            mrun[i] = newm;
            nm[i] = newm;
        }

        __syncthreads();   // S-GEMM reads of Kst complete block-wide before Ss stores

        #pragma unroll
        for (int i = 0; i < 4; i++) {
            float ps = 0.0f;
            #pragma unroll
            for (int j = 0; j < 4; j++) {
                float p = __expf(s[i][j] - nm[i]);
                // duplicated P store: {p,p} so PV loads packed dup pairs
                *(float2*)&Ss[(ty * 4 + i) * SSD + 2 * (tx * 4 + j)] = make_float2(p, p);
                ps += p;
            }
            #pragma unroll
            for (int m = 8; m >= 1; m >>= 1)
                ps += __shfl_xor_sync(0xffffffffu, ps, m);
            lrun[i] = lrun[i] * cfix[i] + ps;
            ull_t cd = pack2(cfix[i], cfix[i]);
            #pragma unroll
            for (int j = 0; j < 4; j++) acc2[i][j] = mul2(acc2[i][j], cd);
        }
        __syncthreads();   // Ss visible

        // O += P @ V, FFMA2 (rows ty*4+i, col-pairs tx*8 + 2*jp)
        #pragma unroll 2
        for (int s2 = 0; s2 < 64; s2++) {
            ull_t p0 = *(const ull_t*)&Ss[(ty * 4 + 0) * SSD + 2 * s2];
            ull_t p1 = *(const ull_t*)&Ss[(ty * 4 + 1) * SSD + 2 * s2];
            ull_t p2 = *(const ull_t*)&Ss[(ty * 4 + 2) * SSD + 2 * s2];
            ull_t p3 = *(const ull_t*)&Ss[(ty * 4 + 3) * SSD + 2 * s2];
            const ulonglong2* vp = (const ulonglong2*)&Vs[s2 * 132 + tx * 8];
            ulonglong2 v01 = vp[0], v23 = vp[1];
            ull_t vd[4] = {v01.x, v01.y, v23.x, v23.y};
            ull_t pd[4] = {p0, p1, p2, p3};
            #pragma unroll
            for (int i = 0; i < 4; i++)
                #pragma unroll
                for (int j = 0; j < 4; j++)
                    acc2[i][j] = fma2(pd[i], vd[j], acc2[i][j]);
        }
    }

    // Epilogue: divide by l, write out
    #pragma unroll
    for (int i = 0; i < 4; i++) {
        int row = q0 + ty * 4 + i;
        float inv_l = 1.0f / lrun[i];
        float o[8];
        #pragma unroll
        for (int j = 0; j < 4; j++) unpack2(acc2[i][j], o[2 * j], o[2 * j + 1]);
        float* dst = out + (size_t)(b * T_ + row) * NQ_ + h * D_ + tx * 8;
        *(float4*)(dst)     = make_float4(o[0] * inv_l, o[1] * inv_l, o[2] * inv_l, o[3] * inv_l);
        *(float4*)(dst + 4) = make_float4(o[4] * inv_l, o[5] * inv_l, o[6] * inv_l, o[7] * inv_l);
    }
}

// ---------------------------------------------------------------------------
extern "C" void kernel_launch(void* const* d_in, const int* in_sizes, int n_in,
                              void* d_out, int out_size)
{
    const float* x   = (const float*)d_in[0];
    const float* wq  = (const float*)d_in[1];
    const float* bq  = (const float*)d_in[2];
    const float* wkv = (const float*)d_in[3];
    const float* bkv = (const float*)d_in[4];
    const float* wo  = (const float*)d_in[5];
    float* out = (float*)d_out;

    float *qbuf, *kvbuf, *attbuf;
    cudaGetSymbolAddress((void**)&qbuf,  g_q);
    cudaGetSymbolAddress((void**)&kvbuf, g_kv);
    cudaGetSymbolAddress((void**)&attbuf, g_att);

    dim3 blk(256);

    // Projections (FFMA2 GEMM, 128x128 tiles)
    gemm_ffma2_kernel<<<dim3(NQ_ / 128, M_ / 128), blk>>>(x, wq, bq, qbuf, NQ_, E_);
    gemm_ffma2_kernel<<<dim3(NKV_ / 128, M_ / 128), blk>>>(x, wkv, bkv, kvbuf, NKV_, E_);

    // Positional encoding into q and k
    add_pe_kernel<<<M_, D_>>>(qbuf, kvbuf);

    // Flash attention
    attn_kernel<<<dim3(T_ / 64, B_ * H_), blk>>>(qbuf, kvbuf, attbuf);

    // Output projection
    gemm_ffma2_kernel<<<dim3(E_ / 128, M_ / 128), blk>>>(attbuf, wo, nullptr, out, E_, NQ_);
}